// round 4
// baseline (speedup 1.0000x reference)
#include <cuda_runtime.h>

#define D    512
#define BLK  512
#define CK   16
#define CHUNK_F (CK * D)
#define GRID 456            // 3 CTAs/SM x 152 SMs (GB300)

__device__ int g_starts[1024];
__device__ int g_counter;

__device__ __forceinline__ void cp16(void* smem_dst, const void* gmem_src) {
    unsigned int s = (unsigned int)__cvta_generic_to_shared(smem_dst);
    asm volatile("cp.async.cg.shared.global [%0], [%1], 16;" :: "r"(s), "l"(gmem_src));
}

// 1-block exclusive scan of lengths -> g_starts; resets steal counter.
__global__ void setup_kernel(const int* __restrict__ lengths, int nseg) {
    __shared__ int s[1024];
    int tid = threadIdx.x;
    int v0 = (tid < nseg) ? lengths[tid] : 0;
    s[tid] = v0;
    __syncthreads();
    for (int off = 1; off < 1024; off <<= 1) {
        int v = (tid >= off) ? s[tid - off] : 0;
        __syncthreads();
        s[tid] += v;
        __syncthreads();
    }
    if (tid < nseg) g_starts[tid] = s[tid] - v0;
    if (tid == 0)   g_counter = 0;
}

// Persistent CTAs, atomic segment stealing, double-buffered cp.async pipeline
// that streams chunks continuously ACROSS segment boundaries.
//   out_t = (sum_{i<=t} e_i * ctx_i) / (sum_{i<=t} e_i),  e_i = exp(ctx_i . theta)
// (per-segment max offset cancels in the ratio; scores are tiny here)
__global__ void __launch_bounds__(BLK)
seg_prefix_softmax(const float* __restrict__ context,
                   const float* __restrict__ theta,
                   const int*   __restrict__ lengths,
                   float*       __restrict__ out,
                   int nseg)
{
    extern __shared__ float s_ctx[];       // 2 * CK * D floats = 64 KB
    __shared__ float s_theta[D];
    __shared__ float s_e[CK];
    __shared__ int4  s_meta[2];            // {valid, newseg, tok, ck}

    const int tid  = threadIdx.x;
    const int lane = tid & 31;
    const int wid  = tid >> 5;

    s_theta[tid] = theta[tid];

    // thread-0-private prefetch cursor
    int cstart = 0, clen = 0, cbase = 0;

    // ---- prologue: steal first segment, prefetch its chunk 0 into slot 0 ----
    if (tid == 0) {
        int sg = atomicAdd(&g_counter, 1);
        if (sg < nseg) {
            cstart = g_starts[sg]; clen = lengths[sg]; cbase = 0;
            s_meta[0] = make_int4(1, 1, cstart, min(CK, clen));
        } else {
            s_meta[0] = make_int4(0, 0, 0, 0);
        }
    }
    __syncthreads();
    if (s_meta[0].x) {
        const float4* src = (const float4*)(context + (size_t)s_meta[0].z * D);
        float4* dst = (float4*)s_ctx;
        const int n4 = s_meta[0].w * (D / 4);
        for (int i = tid; i < n4; i += BLK) cp16(dst + i, src + i);
    }
    asm volatile("cp.async.commit_group;");

    float num = 0.f, den = 0.f;
    int cs = 0;

    for (;;) {
        const int4 m = s_meta[cs];
        if (!m.x) break;

        // ---- thread 0: advance cursor (steal new segment if needed), write meta ----
        if (tid == 0) {
            cbase += CK;
            int nnew = 0, valid = 1;
            if (cbase >= clen) {
                int sg = atomicAdd(&g_counter, 1);
                if (sg < nseg) {
                    cstart = g_starts[sg]; clen = lengths[sg]; cbase = 0; nnew = 1;
                } else valid = 0;
            }
            s_meta[cs ^ 1] = valid ? make_int4(1, nnew, cstart + cbase, min(CK, clen - cbase))
                                   : make_int4(0, 0, 0, 0);
        }
        __syncthreads();

        // ---- prefetch next chunk into other slot ----
        {
            const int4 nm = s_meta[cs ^ 1];
            if (nm.x) {
                const float4* src = (const float4*)(context + (size_t)nm.z * D);
                float4* dst = (float4*)(s_ctx + (cs ^ 1) * CHUNK_F);
                const int n4 = nm.w * (D / 4);
                for (int i = tid; i < n4; i += BLK) cp16(dst + i, src + i);
            }
        }
        asm volatile("cp.async.commit_group;");
        asm volatile("cp.async.wait_group 1;");   // current slot landed
        __syncthreads();

        // ---- compute current slot ----
        const float* buf = s_ctx + cs * CHUNK_F;
        if (m.y) { num = 0.f; den = 0.f; }        // new segment: reset prefix state

        if (wid < m.w) {                          // scores: warp w -> token w
            const float* row = buf + wid * D;
            float p = 0.f;
            #pragma unroll
            for (int k = 0; k < D / 32; k++) {
                const int j = lane + k * 32;
                p = fmaf(row[j], s_theta[j], p);
            }
            #pragma unroll
            for (int o = 16; o > 0; o >>= 1)
                p += __shfl_down_sync(0xffffffffu, p, o);
            if (lane == 0) s_e[wid] = __expf(p);
        }
        __syncthreads();

        float* orow = out + ((size_t)m.z * D + tid);
        #pragma unroll 4
        for (int t = 0; t < m.w; t++) {
            const float e = s_e[t];
            den += e;
            num = fmaf(e, buf[t * D + tid], num);
            __stcs(orow + (size_t)t * D, __fdividef(num, den));
        }
        __syncthreads();   // slot fully consumed: safe to overwrite buf & meta

        cs ^= 1;
    }
}

extern "C" void kernel_launch(void* const* d_in, const int* in_sizes, int n_in,
                              void* d_out, int out_size) {
    const float* context = (const float*)d_in[0];   // [T, 512]
    const float* theta   = (const float*)d_in[1];   // [512, 1]
    const int*   lengths = (const int*)d_in[2];     // [B]
    const int nseg = in_sizes[2];

    cudaFuncSetAttribute(seg_prefix_softmax,
                         cudaFuncAttributeMaxDynamicSharedMemorySize,
                         2 * CHUNK_F * (int)sizeof(float));

    setup_kernel<<<1, 1024>>>(lengths, nseg);
    seg_prefix_softmax<<<GRID, BLK, 2 * CHUNK_F * sizeof(float)>>>(
        context, theta, lengths, (float*)d_out, nseg);
}